// round 11
// baseline (speedup 1.0000x reference)
#include <cuda_runtime.h>

// Problem constants (fixed shapes)
#define T_TOK 8192
#define D_IN  1024
#define H1    128
#define QDIM  32
#define HALFD 8
#define KNN   8
#define NKEYS 256

// GEMM tiling: 32 tokens x 128 outputs per block, BK=16, 128 threads.
#define BM 32
#define BN 128
#define BK 16
#define NKT (D_IN / BK)   // 64

// Scratch (device globals: allocation-free rule)
__device__ __align__(16) float g_h[T_TOK * H1];     // 4 MB (relu'd hidden)
__device__ float g_wt[T_TOK * 16];                  // 512 KB
__device__ int   g_id[T_TOK * 16];                  // 512 KB

// Packed dual-fp32 FMA (B300 FFMA2 path)
#define FMA2(d, a, b) asm("fma.rn.f32x2 %0, %1, %2, %0;" : "+l"(d) : "l"(a), "l"(b))

// ---------------------------------------------------------------------------
// Kernel 1: h = relu(x @ W1^T + b1)
//   grid 256 (2 CTAs/SM -> 2 warps/SMSP), 128 threads.
//   Xs [k][tok] (STS bank = lane, conflict-free), Ws [k][colpair] float4 with
//   duplicated (w,w) pairs so one LDS.128 feeds two FMA2 columns.
//   Per k-step: 1 LDS.128 (X) + 4 LDS.128 (W) + 16 FMA2.
// ---------------------------------------------------------------------------
__global__ __launch_bounds__(128, 1)
void k1_gemm_relu(const float* __restrict__ x, const float* __restrict__ W1,
                  const float* __restrict__ b1)
{
    __shared__ __align__(16) float  Xs[2][BK * BM];          // 2 x 2 KB
    __shared__ __align__(16) float4 Ws[2][BK * (BN / 2)];    // 2 x 16 KB

    const int tid  = threadIdx.x;
    const int lane = tid & 31;
    const int w    = tid >> 5;     // warp 0..3
    const int tx   = tid & 15;     // col-pair group
    const int ty   = tid >> 4;     // token quad 0..7
    const int t0   = blockIdx.x * BM;

    // Loader mapping
    const int xk  = w << 2;                   // X k-offset (one float4 per thread)
    const int wc0 = lane + ((w & 1) << 5);    // W col base; second col = +64
    const int wk0 = (w >> 1) << 2;            // W k-offset base; second quad = +8
    const int kqA = (w >> 1);                 // k-quad indices
    const int kqB = (w >> 1) + 2;

    const float* xp  = x  + (size_t)(t0 + lane) * D_IN + xk;
    const float* wp0 = W1 + (size_t)wc0 * D_IN + wk0;
    const float* wp1 = W1 + (size_t)(wc0 + 64) * D_IN + wk0;

    unsigned long long acc[2][8];
#pragma unroll
    for (int i = 0; i < 2; i++)
#pragma unroll
        for (int j = 0; j < 8; j++) acc[i][j] = 0ull;

    float4 px, pw00, pw01, pw10, pw11;

    // Prefetch tile 0
    px   = *(const float4*)(xp);
    pw00 = *(const float4*)(wp0);
    pw01 = *(const float4*)(wp0 + 8);
    pw10 = *(const float4*)(wp1);
    pw11 = *(const float4*)(wp1 + 8);

    // STS helpers: Xs bank = lane (conflict-free); Ws contiguous 8B per lane.
#define STW(buf, kq, col, v)                                                    \
    do {                                                                        \
        float2* wsp = (float2*)&Ws[buf][0];                                     \
        const int base = (((kq) << 2) * 64 + ((col) >> 1)) * 2 + ((col) & 1);   \
        wsp[base + 0 * 128] = make_float2((v).x, (v).x);                        \
        wsp[base + 1 * 128] = make_float2((v).y, (v).y);                        \
        wsp[base + 2 * 128] = make_float2((v).z, (v).z);                        \
        wsp[base + 3 * 128] = make_float2((v).w, (v).w);                        \
    } while (0)

#define STORE_TILE(buf)                                                         \
    do {                                                                        \
        Xs[buf][(xk + 0) * BM + lane] = px.x;                                   \
        Xs[buf][(xk + 1) * BM + lane] = px.y;                                   \
        Xs[buf][(xk + 2) * BM + lane] = px.z;                                   \
        Xs[buf][(xk + 3) * BM + lane] = px.w;                                   \
        STW(buf, kqA, wc0,      pw00);                                          \
        STW(buf, kqB, wc0,      pw01);                                          \
        STW(buf, kqA, wc0 + 64, pw10);                                          \
        STW(buf, kqB, wc0 + 64, pw11);                                          \
    } while (0)

    STORE_TILE(0);
    __syncthreads();

#pragma unroll 1
    for (int kt = 0; kt < NKT; kt++) {
        const int cur = kt & 1;
        if (kt < NKT - 1) {
            const int k0 = (kt + 1) * BK;
            px   = *(const float4*)(xp + k0);
            pw00 = *(const float4*)(wp0 + k0);
            pw01 = *(const float4*)(wp0 + k0 + 8);
            pw10 = *(const float4*)(wp1 + k0);
            pw11 = *(const float4*)(wp1 + k0 + 8);
        }
#pragma unroll
        for (int k = 0; k < BK; k++) {
            const ulonglong2 aa =
                *(const ulonglong2*)&Xs[cur][k * BM + (ty << 2)];
#pragma unroll
            for (int c = 0; c < 4; c++) {
                const ulonglong2 bb =
                    *(const ulonglong2*)&Ws[cur][k * 64 + tx + (c << 4)];
                FMA2(acc[0][2 * c],     aa.x, bb.x);
                FMA2(acc[0][2 * c + 1], aa.x, bb.y);
                FMA2(acc[1][2 * c],     aa.y, bb.x);
                FMA2(acc[1][2 * c + 1], aa.y, bb.y);
            }
        }
        if (kt < NKT - 1) STORE_TILE(cur ^ 1);
        __syncthreads();
    }

    // Epilogue: bias + relu
#pragma unroll
    for (int c = 0; c < 4; c++) {
#pragma unroll
        for (int par = 0; par < 2; par++) {
            const int j = (tx << 1) + (c << 5) + par;
            const float bias = __ldg(b1 + j);
#pragma unroll
            for (int i = 0; i < 2; i++) {
                const unsigned long long v = acc[i][2 * c + par];
                const int r = t0 + (ty << 2) + (i << 1);
                const float lo = __uint_as_float((unsigned)(v & 0xffffffffull)) + bias;
                const float hi = __uint_as_float((unsigned)(v >> 32)) + bias;
                g_h[(size_t)r * H1 + j]       = fmaxf(lo, 0.0f);
                g_h[(size_t)(r + 1) * H1 + j] = fmaxf(hi, 0.0f);
            }
        }
    }
}

// ---------------------------------------------------------------------------
// Kernel 3 (fused q-projection + top-k + combine + softmax).
// Warp per token. q_c computed per-lane from L1-resident W2 rows.
// Tie-breaking matches lax.top_k (lowest index first).
// ---------------------------------------------------------------------------
__global__ __launch_bounds__(256, 1)
void k3_topk(const float* __restrict__ keys, const float* __restrict__ W2,
             const float* __restrict__ b2)
{
    __shared__ __align__(16) float ks[2 * 2 * NKEYS * HALFD];   // 32 KB
    __shared__ __align__(16) float hs[8][H1];                   // 4 KB
    __shared__ float sc_s[8][2][2][KNN];
    __shared__ int   id_s[8][2][2][KNN];
    __shared__ float fsc_s[8][2][KNN];
    __shared__ int   fid_s[8][2][KNN];

    const int tid = threadIdx.x;
    for (int i = tid; i < 2 * 2 * NKEYS * HALFD; i += 256) ks[i] = keys[i];
    __syncthreads();

    const int w    = tid >> 5;
    const int lane = tid & 31;
    const int t    = blockIdx.x * 8 + w;
    const float NEGINF = __uint_as_float(0xff800000u);

    // ---- fused k2: q[lane] = b2[lane] + h[t] . W2[lane,:] ----
    ((float4*)&hs[w][0])[lane] =
        *(const float4*)(g_h + (size_t)t * H1 + (lane << 2));
    __syncwarp();

    float myq = __ldg(b2 + lane);
    {
        const float4* w2r = (const float4*)(W2 + (size_t)lane * H1);
#pragma unroll
        for (int j4 = 0; j4 < H1 / 4; j4++) {
            const float4 wv = __ldg(w2r + j4);
            const float4 h4 = *(const float4*)&hs[w][j4 << 2];
            myq = fmaf(h4.x, wv.x, myq);
            myq = fmaf(h4.y, wv.y, myq);
            myq = fmaf(h4.z, wv.z, myq);
            myq = fmaf(h4.w, wv.w, myq);
        }
    }
    __syncwarp();

    // ---- 4 units: (head, side) top-8 of 256 ----
#pragma unroll
    for (int u = 0; u < 4; u++) {
        const int h = u >> 1, side = u & 1;
        float qv[HALFD];
#pragma unroll
        for (int c = 0; c < HALFD; c++)
            qv[c] = __shfl_sync(0xffffffffu, myq, h * 16 + side * 8 + c);

        float s[8];  // lane owns keys n = i*32 + lane
#pragma unroll
        for (int i = 0; i < 8; i++) {
            const int n = i * 32 + lane;
            const float4 k0 = *(const float4*)&ks[(u * NKEYS + n) * HALFD];
            const float4 k1 = *(const float4*)&ks[(u * NKEYS + n) * HALFD + 4];
            s[i] = qv[0] * k0.x + qv[1] * k0.y + qv[2] * k0.z + qv[3] * k0.w
                 + qv[4] * k1.x + qv[5] * k1.y + qv[6] * k1.z + qv[7] * k1.w;
        }
#pragma unroll
        for (int r = 0; r < KNN; r++) {
            float bv = NEGINF; int bn = 0x7fffffff;
#pragma unroll
            for (int i = 0; i < 8; i++)
                if (s[i] > bv) { bv = s[i]; bn = i * 32 + lane; }
#pragma unroll
            for (int off = 16; off; off >>= 1) {
                const float ov = __shfl_xor_sync(0xffffffffu, bv, off);
                const int   on = __shfl_xor_sync(0xffffffffu, bn, off);
                if (ov > bv || (ov == bv && on < bn)) { bv = ov; bn = on; }
            }
            if (lane == 0) { sc_s[w][h][side][r] = bv; id_s[w][h][side][r] = bn; }
            if ((bn & 31) == lane) s[bn >> 5] = NEGINF;   // kill winner
        }
    }
    __syncwarp();

    // ---- Combine per head: 64 combos, top-8 ----
#pragma unroll
    for (int h = 0; h < 2; h++) {
        float v0 = sc_s[w][h][0][lane >> 3]       + sc_s[w][h][1][lane & 7];
        float v1 = sc_s[w][h][0][(lane >> 3) + 4] + sc_s[w][h][1][lane & 7];
#pragma unroll
        for (int r = 0; r < KNN; r++) {
            float bv = v0; int bc = lane;
            if (v1 > bv) { bv = v1; bc = lane + 32; }
#pragma unroll
            for (int off = 16; off; off >>= 1) {
                const float ov = __shfl_xor_sync(0xffffffffu, bv, off);
                const int   oc = __shfl_xor_sync(0xffffffffu, bc, off);
                if (ov > bv || (ov == bv && oc < bc)) { bv = ov; bc = oc; }
            }
            if (lane == 0) {
                fsc_s[w][h][r] = bv;
                const int a = bc >> 3, b = bc & 7;
                fid_s[w][h][r] = id_s[w][h][0][a] * NKEYS + id_s[w][h][1][b];
            }
            if (bc == lane)      v0 = NEGINF;
            if (bc == lane + 32) v1 = NEGINF;
        }
    }
    __syncwarp();

    // ---- softmax over 8 per head ----
    if (lane < 16) {
        const int h = lane >> 3, kk = lane & 7;
        float m = NEGINF;
#pragma unroll
        for (int i = 0; i < KNN; i++) m = fmaxf(m, fsc_s[w][h][i]);
        float den = 0.f;
#pragma unroll
        for (int i = 0; i < KNN; i++) den += expf(fsc_s[w][h][i] - m);
        const float wt = expf(fsc_s[w][h][kk] - m) / den;
        g_wt[t * 16 + lane] = wt;
        g_id[t * 16 + lane] = fid_s[w][h][kk];
    }
}

// ---------------------------------------------------------------------------
// Kernel 4: out[t] = sum_{k<16} w_k * values[idx_k]
// Persistent blocks (grid = 148*3 to match reg-limited occupancy), double-
// buffered metadata, 16-deep independent LDG.128 per thread.
// ---------------------------------------------------------------------------
#define K4_GRID 444

__global__ __launch_bounds__(256)
void k4_gather(const float* __restrict__ values, float* __restrict__ out)
{
    __shared__ float ws[2][16];
    __shared__ int   is[2][16];

    const int tid = threadIdx.x;
    const int col = tid << 2;

    int t = blockIdx.x;
    if (tid < 16) {
        ws[0][tid] = g_wt[t * 16 + tid];
        is[0][tid] = g_id[t * 16 + tid];
    }
    __syncthreads();

    int buf = 0;
    for (; t < T_TOK; t += K4_GRID, buf ^= 1) {
        const int tn = t + K4_GRID;
        if (tid < 16 && tn < T_TOK) {
            ws[buf ^ 1][tid] = g_wt[tn * 16 + tid];
            is[buf ^ 1][tid] = g_id[tn * 16 + tid];
        }
        float4 acc = make_float4(0.f, 0.f, 0.f, 0.f);
#pragma unroll
        for (int k = 0; k < 16; k++) {
            const float4 v =
                __ldg((const float4*)(values + (size_t)is[buf][k] * D_IN + col));
            const float wk = ws[buf][k];
            acc.x = fmaf(wk, v.x, acc.x);
            acc.y = fmaf(wk, v.y, acc.y);
            acc.z = fmaf(wk, v.z, acc.z);
            acc.w = fmaf(wk, v.w, acc.w);
        }
        *(float4*)(out + (size_t)t * D_IN + col) = acc;
        __syncthreads();
    }
}

// ---------------------------------------------------------------------------
extern "C" void kernel_launch(void* const* d_in, const int* in_sizes, int n_in,
                              void* d_out, int out_size)
{
    const float* x      = (const float*)d_in[0];
    const float* W1     = (const float*)d_in[1];
    const float* b1     = (const float*)d_in[2];
    const float* W2     = (const float*)d_in[3];
    const float* b2     = (const float*)d_in[4];
    const float* keys   = (const float*)d_in[5];
    const float* values = (const float*)d_in[6];
    float* out = (float*)d_out;

    k1_gemm_relu<<<T_TOK / BM, 128>>>(x, W1, b1);
    k3_topk<<<T_TOK / 8, 256>>>(keys, W2, b2);
    k4_gather<<<K4_GRID, 256>>>(values, out);
}

// round 12
// speedup vs baseline: 1.0079x; 1.0079x over previous
#include <cuda_runtime.h>

// Problem constants (fixed shapes)
#define T_TOK 8192
#define D_IN  1024
#define H1    128
#define QDIM  32
#define HALFD 8
#define KNN   8
#define NKEYS 256

// GEMM tiling: 32 tokens x 128 outputs per block, BK=16, 128 threads.
#define BM 32
#define BN 128
#define BK 16
#define NKT (D_IN / BK)   // 64

// Scratch (device globals: allocation-free rule)
__device__ __align__(16) float g_h[T_TOK * H1];     // 4 MB (relu'd hidden)
__device__ float g_wt[T_TOK * 16];                  // 512 KB
__device__ int   g_id[T_TOK * 16];                  // 512 KB

// Packed dual-fp32 FMA (B300 FFMA2 path)
#define FMA2(d, a, b) asm("fma.rn.f32x2 %0, %1, %2, %0;" : "+l"(d) : "l"(a), "l"(b))

// ---------------------------------------------------------------------------
// Kernel 1: h = relu(x @ W1^T + b1)
//   grid 256 (2 CTAs/SM -> 2 warps/SMSP), 128 threads.
//   Xs [k][tok] (STS bank = lane, conflict-free), Ws [k][colpair] float4 with
//   duplicated (w,w) pairs so one LDS.128 feeds two FMA2 columns.
//   Per k-step: 1 LDS.128 (X) + 4 LDS.128 (W) + 16 FMA2.
// ---------------------------------------------------------------------------
__global__ __launch_bounds__(128, 1)
void k1_gemm_relu(const float* __restrict__ x, const float* __restrict__ W1,
                  const float* __restrict__ b1)
{
    __shared__ __align__(16) float  Xs[2][BK * BM];          // 2 x 2 KB
    __shared__ __align__(16) float4 Ws[2][BK * (BN / 2)];    // 2 x 16 KB

    const int tid  = threadIdx.x;
    const int lane = tid & 31;
    const int w    = tid >> 5;     // warp 0..3
    const int tx   = tid & 15;     // col-pair group
    const int ty   = tid >> 4;     // token quad 0..7
    const int t0   = blockIdx.x * BM;

    // Loader mapping
    const int xk  = w << 2;                   // X k-offset (one float4 per thread)
    const int wc0 = lane + ((w & 1) << 5);    // W col base; second col = +64
    const int wk0 = (w >> 1) << 2;            // W k-offset base; second quad = +8
    const int kqA = (w >> 1);                 // k-quad indices
    const int kqB = (w >> 1) + 2;

    const float* xp  = x  + (size_t)(t0 + lane) * D_IN + xk;
    const float* wp0 = W1 + (size_t)wc0 * D_IN + wk0;
    const float* wp1 = W1 + (size_t)(wc0 + 64) * D_IN + wk0;

    unsigned long long acc[2][8];
#pragma unroll
    for (int i = 0; i < 2; i++)
#pragma unroll
        for (int j = 0; j < 8; j++) acc[i][j] = 0ull;

    float4 px, pw00, pw01, pw10, pw11;

    // Prefetch tile 0
    px   = *(const float4*)(xp);
    pw00 = *(const float4*)(wp0);
    pw01 = *(const float4*)(wp0 + 8);
    pw10 = *(const float4*)(wp1);
    pw11 = *(const float4*)(wp1 + 8);

    // STS helpers: Xs bank = lane (conflict-free); Ws contiguous 8B per lane.
#define STW(buf, kq, col, v)                                                    \
    do {                                                                        \
        float2* wsp = (float2*)&Ws[buf][0];                                     \
        const int base = (((kq) << 2) * 64 + ((col) >> 1)) * 2 + ((col) & 1);   \
        wsp[base + 0 * 128] = make_float2((v).x, (v).x);                        \
        wsp[base + 1 * 128] = make_float2((v).y, (v).y);                        \
        wsp[base + 2 * 128] = make_float2((v).z, (v).z);                        \
        wsp[base + 3 * 128] = make_float2((v).w, (v).w);                        \
    } while (0)

#define STORE_TILE(buf)                                                         \
    do {                                                                        \
        Xs[buf][(xk + 0) * BM + lane] = px.x;                                   \
        Xs[buf][(xk + 1) * BM + lane] = px.y;                                   \
        Xs[buf][(xk + 2) * BM + lane] = px.z;                                   \
        Xs[buf][(xk + 3) * BM + lane] = px.w;                                   \
        STW(buf, kqA, wc0,      pw00);                                          \
        STW(buf, kqB, wc0,      pw01);                                          \
        STW(buf, kqA, wc0 + 64, pw10);                                          \
        STW(buf, kqB, wc0 + 64, pw11);                                          \
    } while (0)

    STORE_TILE(0);
    __syncthreads();

#pragma unroll 1
    for (int kt = 0; kt < NKT; kt++) {
        const int cur = kt & 1;
        if (kt < NKT - 1) {
            const int k0 = (kt + 1) * BK;
            px   = *(const float4*)(xp + k0);
            pw00 = *(const float4*)(wp0 + k0);
            pw01 = *(const float4*)(wp0 + k0 + 8);
            pw10 = *(const float4*)(wp1 + k0);
            pw11 = *(const float4*)(wp1 + k0 + 8);
        }
#pragma unroll
        for (int k = 0; k < BK; k++) {
            const ulonglong2 aa =
                *(const ulonglong2*)&Xs[cur][k * BM + (ty << 2)];
#pragma unroll
            for (int c = 0; c < 4; c++) {
                const ulonglong2 bb =
                    *(const ulonglong2*)&Ws[cur][k * 64 + tx + (c << 4)];
                FMA2(acc[0][2 * c],     aa.x, bb.x);
                FMA2(acc[0][2 * c + 1], aa.x, bb.y);
                FMA2(acc[1][2 * c],     aa.y, bb.x);
                FMA2(acc[1][2 * c + 1], aa.y, bb.y);
            }
        }
        if (kt < NKT - 1) STORE_TILE(cur ^ 1);
        __syncthreads();
    }

    // Epilogue: bias + relu
#pragma unroll
    for (int c = 0; c < 4; c++) {
#pragma unroll
        for (int par = 0; par < 2; par++) {
            const int j = (tx << 1) + (c << 5) + par;
            const float bias = __ldg(b1 + j);
#pragma unroll
            for (int i = 0; i < 2; i++) {
                const unsigned long long v = acc[i][2 * c + par];
                const int r = t0 + (ty << 2) + (i << 1);
                const float lo = __uint_as_float((unsigned)(v & 0xffffffffull)) + bias;
                const float hi = __uint_as_float((unsigned)(v >> 32)) + bias;
                g_h[(size_t)r * H1 + j]       = fmaxf(lo, 0.0f);
                g_h[(size_t)(r + 1) * H1 + j] = fmaxf(hi, 0.0f);
            }
        }
    }
}

// ---------------------------------------------------------------------------
// Kernel 3 (fused q-projection + top-k + combine + softmax).
// Warp per token. q_c computed per-lane from L1-resident W2 rows.
// Tie-breaking matches lax.top_k (lowest index first).
// ---------------------------------------------------------------------------
__global__ __launch_bounds__(256, 1)
void k3_topk(const float* __restrict__ keys, const float* __restrict__ W2,
             const float* __restrict__ b2)
{
    __shared__ __align__(16) float ks[2 * 2 * NKEYS * HALFD];   // 32 KB
    __shared__ __align__(16) float hs[8][H1];                   // 4 KB
    __shared__ float sc_s[8][2][2][KNN];
    __shared__ int   id_s[8][2][2][KNN];
    __shared__ float fsc_s[8][2][KNN];
    __shared__ int   fid_s[8][2][KNN];

    const int tid = threadIdx.x;
    for (int i = tid; i < 2 * 2 * NKEYS * HALFD; i += 256) ks[i] = keys[i];
    __syncthreads();

    const int w    = tid >> 5;
    const int lane = tid & 31;
    const int t    = blockIdx.x * 8 + w;
    const float NEGINF = __uint_as_float(0xff800000u);

    // ---- fused k2: q[lane] = b2[lane] + h[t] . W2[lane,:] ----
    ((float4*)&hs[w][0])[lane] =
        *(const float4*)(g_h + (size_t)t * H1 + (lane << 2));
    __syncwarp();

    float myq = __ldg(b2 + lane);
    {
        const float4* w2r = (const float4*)(W2 + (size_t)lane * H1);
#pragma unroll
        for (int j4 = 0; j4 < H1 / 4; j4++) {
            const float4 wv = __ldg(w2r + j4);
            const float4 h4 = *(const float4*)&hs[w][j4 << 2];
            myq = fmaf(h4.x, wv.x, myq);
            myq = fmaf(h4.y, wv.y, myq);
            myq = fmaf(h4.z, wv.z, myq);
            myq = fmaf(h4.w, wv.w, myq);
        }
    }
    __syncwarp();

    // ---- 4 units: (head, side) top-8 of 256 ----
#pragma unroll
    for (int u = 0; u < 4; u++) {
        const int h = u >> 1, side = u & 1;
        float qv[HALFD];
#pragma unroll
        for (int c = 0; c < HALFD; c++)
            qv[c] = __shfl_sync(0xffffffffu, myq, h * 16 + side * 8 + c);

        float s[8];  // lane owns keys n = i*32 + lane
#pragma unroll
        for (int i = 0; i < 8; i++) {
            const int n = i * 32 + lane;
            const float4 k0 = *(const float4*)&ks[(u * NKEYS + n) * HALFD];
            const float4 k1 = *(const float4*)&ks[(u * NKEYS + n) * HALFD + 4];
            s[i] = qv[0] * k0.x + qv[1] * k0.y + qv[2] * k0.z + qv[3] * k0.w
                 + qv[4] * k1.x + qv[5] * k1.y + qv[6] * k1.z + qv[7] * k1.w;
        }
#pragma unroll
        for (int r = 0; r < KNN; r++) {
            float bv = NEGINF; int bn = 0x7fffffff;
#pragma unroll
            for (int i = 0; i < 8; i++)
                if (s[i] > bv) { bv = s[i]; bn = i * 32 + lane; }
#pragma unroll
            for (int off = 16; off; off >>= 1) {
                const float ov = __shfl_xor_sync(0xffffffffu, bv, off);
                const int   on = __shfl_xor_sync(0xffffffffu, bn, off);
                if (ov > bv || (ov == bv && on < bn)) { bv = ov; bn = on; }
            }
            if (lane == 0) { sc_s[w][h][side][r] = bv; id_s[w][h][side][r] = bn; }
            if ((bn & 31) == lane) s[bn >> 5] = NEGINF;   // kill winner
        }
    }
    __syncwarp();

    // ---- Combine per head: 64 combos, top-8 ----
#pragma unroll
    for (int h = 0; h < 2; h++) {
        float v0 = sc_s[w][h][0][lane >> 3]       + sc_s[w][h][1][lane & 7];
        float v1 = sc_s[w][h][0][(lane >> 3) + 4] + sc_s[w][h][1][lane & 7];
#pragma unroll
        for (int r = 0; r < KNN; r++) {
            float bv = v0; int bc = lane;
            if (v1 > bv) { bv = v1; bc = lane + 32; }
#pragma unroll
            for (int off = 16; off; off >>= 1) {
                const float ov = __shfl_xor_sync(0xffffffffu, bv, off);
                const int   oc = __shfl_xor_sync(0xffffffffu, bc, off);
                if (ov > bv || (ov == bv && oc < bc)) { bv = ov; bc = oc; }
            }
            if (lane == 0) {
                fsc_s[w][h][r] = bv;
                const int a = bc >> 3, b = bc & 7;
                fid_s[w][h][r] = id_s[w][h][0][a] * NKEYS + id_s[w][h][1][b];
            }
            if (bc == lane)      v0 = NEGINF;
            if (bc == lane + 32) v1 = NEGINF;
        }
    }
    __syncwarp();

    // ---- softmax over 8 per head ----
    if (lane < 16) {
        const int h = lane >> 3, kk = lane & 7;
        float m = NEGINF;
#pragma unroll
        for (int i = 0; i < KNN; i++) m = fmaxf(m, fsc_s[w][h][i]);
        float den = 0.f;
#pragma unroll
        for (int i = 0; i < KNN; i++) den += expf(fsc_s[w][h][i] - m);
        const float wt = expf(fsc_s[w][h][kk] - m) / den;
        g_wt[t * 16 + lane] = wt;
        g_id[t * 16 + lane] = fid_s[w][h][kk];
    }
}

// ---------------------------------------------------------------------------
// Kernel 4: out[t] = sum_{k<16} w_k * values[idx_k]
// Persistent blocks (grid = 148*3 to match reg-limited occupancy), double-
// buffered metadata, 16-deep independent LDG.128 per thread.
// ---------------------------------------------------------------------------
#define K4_GRID 444

__global__ __launch_bounds__(256)
void k4_gather(const float* __restrict__ values, float* __restrict__ out)
{
    __shared__ float ws[2][16];
    __shared__ int   is[2][16];

    const int tid = threadIdx.x;
    const int col = tid << 2;

    int t = blockIdx.x;
    if (tid < 16) {
        ws[0][tid] = g_wt[t * 16 + tid];
        is[0][tid] = g_id[t * 16 + tid];
    }
    __syncthreads();

    int buf = 0;
    for (; t < T_TOK; t += K4_GRID, buf ^= 1) {
        const int tn = t + K4_GRID;
        if (tid < 16 && tn < T_TOK) {
            ws[buf ^ 1][tid] = g_wt[tn * 16 + tid];
            is[buf ^ 1][tid] = g_id[tn * 16 + tid];
        }
        float4 acc = make_float4(0.f, 0.f, 0.f, 0.f);
#pragma unroll
        for (int k = 0; k < 16; k++) {
            const float4 v =
                __ldg((const float4*)(values + (size_t)is[buf][k] * D_IN + col));
            const float wk = ws[buf][k];
            acc.x = fmaf(wk, v.x, acc.x);
            acc.y = fmaf(wk, v.y, acc.y);
            acc.z = fmaf(wk, v.z, acc.z);
            acc.w = fmaf(wk, v.w, acc.w);
        }
        *(float4*)(out + (size_t)t * D_IN + col) = acc;
        __syncthreads();
    }
}

// ---------------------------------------------------------------------------
extern "C" void kernel_launch(void* const* d_in, const int* in_sizes, int n_in,
                              void* d_out, int out_size)
{
    const float* x      = (const float*)d_in[0];
    const float* W1     = (const float*)d_in[1];
    const float* b1     = (const float*)d_in[2];
    const float* W2     = (const float*)d_in[3];
    const float* b2     = (const float*)d_in[4];
    const float* keys   = (const float*)d_in[5];
    const float* values = (const float*)d_in[6];
    float* out = (float*)d_out;

    k1_gemm_relu<<<T_TOK / BM, 128>>>(x, W1, b1);
    k3_topk<<<T_TOK / 8, 256>>>(keys, W2, b2);
    k4_gather<<<K4_GRID, 256>>>(values, out);
}

// round 13
// speedup vs baseline: 1.3889x; 1.3779x over previous
#include <cuda_runtime.h>

// Problem constants (fixed shapes)
#define T_TOK 8192
#define D_IN  1024
#define H1    128
#define QDIM  32
#define HALFD 8
#define KNN   8
#define NKEYS 256

// GEMM tiling: 64 tokens x 128 outputs per block, BK=16, 256 threads.
#define BM 64
#define BN 128
#define BK 16
#define NKT (D_IN / BK)   // 64

// Scratch (device globals: allocation-free rule)
__device__ __align__(16) float g_h[T_TOK * H1];     // 4 MB
__device__ __align__(16) float g_q[T_TOK * QDIM];   // 1 MB
__device__ float g_wt[T_TOK * 16];                  // 512 KB
__device__ int   g_id[T_TOK * 16];                  // 512 KB

// Packed dual-fp32 FMA (B300 FFMA2 path, single issue slot, rt=2)
#define FMA2(d, a, b) asm("fma.rn.f32x2 %0, %1, %2, %0;" : "+l"(d) : "l"(a), "l"(b))
// Duplicate a scalar float into both halves of a 64-bit packed operand (alu pipe)
#define DUP2(d, s)    asm("mov.b64 %0, {%1, %1};" : "=l"(d) : "f"(s))

// ---------------------------------------------------------------------------
// Kernel 1: h = relu(x @ W1^T + b1)   [8192x1024]@[1024x128]
//   256 threads (8 warps = 2/SMSP), grid 128 (one wave).
//   Xs[k][t], Ws[k][j] both k-major, NO duplication in smem.
//   Thread tile: 8 tokens (4 natural f32x2 pairs) x 4 cols.
//   Per k-step/thread: 2 broadcast LDS.128 (a) + 1 LDS.128 (b) + 4 DUP2 (alu)
//   + 16 FMA2 (fma).  L1: 6 wavefronts/warp/k vs fma 32 cyc -> fma-bound.
// ---------------------------------------------------------------------------
__global__ __launch_bounds__(256, 1)
void k1_gemm_relu(const float* __restrict__ x, const float* __restrict__ W1,
                  const float* __restrict__ b1)
{
    __shared__ __align__(16) float Xs[2][BK][BM];   // 2 x 4 KB
    __shared__ __align__(16) float Ws[2][BK][BN];   // 2 x 8 KB

    const int tid = threadIdx.x;
    const int tx  = tid & 31;   // col group: cols tx*4 .. tx*4+3
    const int ty  = tid >> 5;   // token group: tokens ty*8 .. ty*8+7 (== warp id)
    const int t0  = blockIdx.x * BM;

    // Loader mapping
    const int xt  = tid & 63;          // X token within tile
    const int xkq = (tid >> 6) << 2;   // X k-offset: 0,4,8,12 (one float4)
    const int wj  = tid & 127;         // W col
    const int wkq = (tid >> 7) << 3;   // W k-offset: 0 or 8 (two float4s)

    const float* xp = x  + (size_t)(t0 + xt) * D_IN + xkq;
    const float* wp = W1 + (size_t)wj * D_IN + wkq;

    unsigned long long acc[4][4];
#pragma unroll
    for (int p = 0; p < 4; p++)
#pragma unroll
        for (int c = 0; c < 4; c++) acc[p][c] = 0ull;

    float4 pX, pW0, pW1;

    // Prefetch tile 0
    pX  = *(const float4*)(xp);
    pW0 = *(const float4*)(wp);
    pW1 = *(const float4*)(wp + 4);

#define STORE_TILE(buf)                                                        \
    do {                                                                       \
        Xs[buf][xkq + 0][xt] = pX.x;                                           \
        Xs[buf][xkq + 1][xt] = pX.y;                                           \
        Xs[buf][xkq + 2][xt] = pX.z;                                           \
        Xs[buf][xkq + 3][xt] = pX.w;                                           \
        Ws[buf][wkq + 0][wj] = pW0.x;                                          \
        Ws[buf][wkq + 1][wj] = pW0.y;                                          \
        Ws[buf][wkq + 2][wj] = pW0.z;                                          \
        Ws[buf][wkq + 3][wj] = pW0.w;                                          \
        Ws[buf][wkq + 4][wj] = pW1.x;                                          \
        Ws[buf][wkq + 5][wj] = pW1.y;                                          \
        Ws[buf][wkq + 6][wj] = pW1.z;                                          \
        Ws[buf][wkq + 7][wj] = pW1.w;                                          \
    } while (0)

    STORE_TILE(0);
    __syncthreads();

#pragma unroll 1
    for (int kt = 0; kt < NKT; kt++) {
        const int cur = kt & 1;
        if (kt < NKT - 1) {
            const int k0 = (kt + 1) * BK;
            pX  = *(const float4*)(xp + k0);
            pW0 = *(const float4*)(wp + k0);
            pW1 = *(const float4*)(wp + k0 + 4);
        }
#pragma unroll
        for (int k = 0; k < BK; k++) {
            // a: 4 natural token pairs (warp-uniform address -> broadcast)
            const ulonglong2 a01 = *(const ulonglong2*)&Xs[cur][k][ty << 3];
            const ulonglong2 a23 = *(const ulonglong2*)&Xs[cur][k][(ty << 3) + 4];
            // b: 4 plain weights, duplicated into packed operands on alu pipe
            const float4 bw = *(const float4*)&Ws[cur][k][tx << 2];
            unsigned long long b0, b1r, b2, b3;
            DUP2(b0,  bw.x);
            DUP2(b1r, bw.y);
            DUP2(b2,  bw.z);
            DUP2(b3,  bw.w);
            FMA2(acc[0][0], a01.x, b0);
            FMA2(acc[0][1], a01.x, b1r);
            FMA2(acc[0][2], a01.x, b2);
            FMA2(acc[0][3], a01.x, b3);
            FMA2(acc[1][0], a01.y, b0);
            FMA2(acc[1][1], a01.y, b1r);
            FMA2(acc[1][2], a01.y, b2);
            FMA2(acc[1][3], a01.y, b3);
            FMA2(acc[2][0], a23.x, b0);
            FMA2(acc[2][1], a23.x, b1r);
            FMA2(acc[2][2], a23.x, b2);
            FMA2(acc[2][3], a23.x, b3);
            FMA2(acc[3][0], a23.y, b0);
            FMA2(acc[3][1], a23.y, b1r);
            FMA2(acc[3][2], a23.y, b2);
            FMA2(acc[3][3], a23.y, b3);
        }
        if (kt < NKT - 1) STORE_TILE(cur ^ 1);
        __syncthreads();
    }

    // Epilogue: bias + relu, vectorized float4 stores (cols tx*4..tx*4+3)
    const float4 bias = __ldg((const float4*)(b1 + (tx << 2)));
#pragma unroll
    for (int p = 0; p < 4; p++) {
        const int t = t0 + (ty << 3) + (p << 1);
        float4 lo, hi;
        lo.x = __uint_as_float((unsigned)(acc[p][0])) + bias.x;
        lo.y = __uint_as_float((unsigned)(acc[p][1])) + bias.y;
        lo.z = __uint_as_float((unsigned)(acc[p][2])) + bias.z;
        lo.w = __uint_as_float((unsigned)(acc[p][3])) + bias.w;
        hi.x = __uint_as_float((unsigned)(acc[p][0] >> 32)) + bias.x;
        hi.y = __uint_as_float((unsigned)(acc[p][1] >> 32)) + bias.y;
        hi.z = __uint_as_float((unsigned)(acc[p][2] >> 32)) + bias.z;
        hi.w = __uint_as_float((unsigned)(acc[p][3] >> 32)) + bias.w;
        lo.x = fmaxf(lo.x, 0.f); lo.y = fmaxf(lo.y, 0.f);
        lo.z = fmaxf(lo.z, 0.f); lo.w = fmaxf(lo.w, 0.f);
        hi.x = fmaxf(hi.x, 0.f); hi.y = fmaxf(hi.y, 0.f);
        hi.z = fmaxf(hi.z, 0.f); hi.w = fmaxf(hi.w, 0.f);
        *(float4*)(g_h + (size_t)t * H1 + (tx << 2))       = lo;
        *(float4*)(g_h + (size_t)(t + 1) * H1 + (tx << 2)) = hi;
    }
}

// ---------------------------------------------------------------------------
// Kernel 2: q = h @ W2^T + b2  (R9-proven version)
// ---------------------------------------------------------------------------
__global__ __launch_bounds__(256, 1)
void k2_q(const float* __restrict__ W2, const float* __restrict__ b2)
{
    __shared__ float W2T[H1 * QDIM];  // [j][c]
    __shared__ float hs[8][H1];

    const int tid  = threadIdx.x;
    const int w    = tid >> 5;
    const int lane = tid & 31;

    for (int i = tid; i < H1 * QDIM; i += 256)
        W2T[(i & (H1 - 1)) * QDIM + (i >> 7)] = W2[i];   // i = c*128 + j
    const float bias = b2[lane];
    __syncthreads();

    for (int g = blockIdx.x; g < T_TOK / 8; g += gridDim.x) {
        const int t = g * 8 + w;
        const float4 hv = *(const float4*)(g_h + (size_t)t * H1 + (lane << 2));
        hs[w][(lane << 2) + 0] = hv.x;
        hs[w][(lane << 2) + 1] = hv.y;
        hs[w][(lane << 2) + 2] = hv.z;
        hs[w][(lane << 2) + 3] = hv.w;
        __syncwarp();
        float acc = bias;
#pragma unroll 16
        for (int j = 0; j < H1; j++)
            acc = fmaf(hs[w][j], W2T[j * QDIM + lane], acc);
        g_q[(size_t)t * QDIM + lane] = acc;
        __syncwarp();
    }
}

// ---------------------------------------------------------------------------
// Kernel 3: scores + top-k + combine + softmax (R9-proven version)
// Tie-breaking matches lax.top_k (lowest index first).
// ---------------------------------------------------------------------------
__global__ __launch_bounds__(256, 1)
void k3_topk(const float* __restrict__ keys)
{
    __shared__ float ks[2 * 2 * NKEYS * HALFD];   // 32 KB
    __shared__ float sc_s[8][2][2][KNN];
    __shared__ int   id_s[8][2][2][KNN];
    __shared__ float fsc_s[8][2][KNN];
    __shared__ int   fid_s[8][2][KNN];

    const int tid = threadIdx.x;
    for (int i = tid; i < 2 * 2 * NKEYS * HALFD; i += 256) ks[i] = keys[i];
    __syncthreads();

    const int w    = tid >> 5;
    const int lane = tid & 31;
    const int t    = blockIdx.x * 8 + w;
    const float myq = g_q[(size_t)t * QDIM + lane];
    const float NEGINF = __uint_as_float(0xff800000u);

    // 4 units: (head, side)
#pragma unroll
    for (int u = 0; u < 4; u++) {
        const int h = u >> 1, side = u & 1;
        float qv[HALFD];
#pragma unroll
        for (int c = 0; c < HALFD; c++)
            qv[c] = __shfl_sync(0xffffffffu, myq, h * 16 + side * 8 + c);

        float s[8];  // lane owns keys n = i*32 + lane
#pragma unroll
        for (int i = 0; i < 8; i++) {
            const int n = i * 32 + lane;
            const float4 k0 = *(const float4*)&ks[(u * NKEYS + n) * HALFD];
            const float4 k1 = *(const float4*)&ks[(u * NKEYS + n) * HALFD + 4];
            s[i] = qv[0] * k0.x + qv[1] * k0.y + qv[2] * k0.z + qv[3] * k0.w
                 + qv[4] * k1.x + qv[5] * k1.y + qv[6] * k1.z + qv[7] * k1.w;
        }
#pragma unroll
        for (int r = 0; r < KNN; r++) {
            float bv = NEGINF; int bn = 0x7fffffff;
#pragma unroll
            for (int i = 0; i < 8; i++)
                if (s[i] > bv) { bv = s[i]; bn = i * 32 + lane; }
#pragma unroll
            for (int off = 16; off; off >>= 1) {
                const float ov = __shfl_xor_sync(0xffffffffu, bv, off);
                const int   on = __shfl_xor_sync(0xffffffffu, bn, off);
                if (ov > bv || (ov == bv && on < bn)) { bv = ov; bn = on; }
            }
            if (lane == 0) { sc_s[w][h][side][r] = bv; id_s[w][h][side][r] = bn; }
            if ((bn & 31) == lane) s[bn >> 5] = NEGINF;   // kill winner
        }
    }
    __syncwarp();

    // Combine per head: 64 combos = sc1[a] + sc2[b], flat c = a*8 + b
#pragma unroll
    for (int h = 0; h < 2; h++) {
        float v0 = sc_s[w][h][0][lane >> 3]       + sc_s[w][h][1][lane & 7];
        float v1 = sc_s[w][h][0][(lane >> 3) + 4] + sc_s[w][h][1][lane & 7];
#pragma unroll
        for (int r = 0; r < KNN; r++) {
            float bv = v0; int bc = lane;
            if (v1 > bv) { bv = v1; bc = lane + 32; }
#pragma unroll
            for (int off = 16; off; off >>= 1) {
                const float ov = __shfl_xor_sync(0xffffffffu, bv, off);
                const int   oc = __shfl_xor_sync(0xffffffffu, bc, off);
                if (ov > bv || (ov == bv && oc < bc)) { bv = ov; bc = oc; }
            }
            if (lane == 0) {
                fsc_s[w][h][r] = bv;
                const int a = bc >> 3, b = bc & 7;
                fid_s[w][h][r] = id_s[w][h][0][a] * NKEYS + id_s[w][h][1][b];
            }
            if (bc == lane)      v0 = NEGINF;
            if (bc == lane + 32) v1 = NEGINF;
        }
    }
    __syncwarp();

    // Softmax over 8 per head; lanes 0..15 each handle one (h,k) output
    if (lane < 16) {
        const int h = lane >> 3, kk = lane & 7;
        float m = NEGINF;
#pragma unroll
        for (int i = 0; i < KNN; i++) m = fmaxf(m, fsc_s[w][h][i]);
        float den = 0.f;
#pragma unroll
        for (int i = 0; i < KNN; i++) den += expf(fsc_s[w][h][i] - m);
        const float wt = expf(fsc_s[w][h][kk] - m) / den;
        g_wt[t * 16 + lane] = wt;
        g_id[t * 16 + lane] = fid_s[w][h][kk];
    }
}

// ---------------------------------------------------------------------------
// Kernel 4: out[t] = sum_{k<16} w_k * values[idx_k]  (R9-proven: 53.7us)
// Block per token, 256 threads, 16-deep independent LDG.128 per thread.
// ---------------------------------------------------------------------------
__global__ __launch_bounds__(256, 1)
void k4_gather(const float* __restrict__ values, float* __restrict__ out)
{
    __shared__ float ws[16];
    __shared__ int   is[16];
    const int t = blockIdx.x;
    if (threadIdx.x < 16) {
        ws[threadIdx.x] = g_wt[t * 16 + threadIdx.x];
        is[threadIdx.x] = g_id[t * 16 + threadIdx.x];
    }
    __syncthreads();
    const int col = threadIdx.x << 2;
    float4 acc = make_float4(0.f, 0.f, 0.f, 0.f);
#pragma unroll
    for (int k = 0; k < 16; k++) {
        const float4 v = __ldg((const float4*)(values + (size_t)is[k] * D_IN + col));
        const float wk = ws[k];
        acc.x = fmaf(wk, v.x, acc.x);
        acc.y = fmaf(wk, v.y, acc.y);
        acc.z = fmaf(wk, v.z, acc.z);
        acc.w = fmaf(wk, v.w, acc.w);
    }
    *(float4*)(out + (size_t)t * D_IN + col) = acc;
}

// ---------------------------------------------------------------------------
extern "C" void kernel_launch(void* const* d_in, const int* in_sizes, int n_in,
                              void* d_out, int out_size)
{
    const float* x      = (const float*)d_in[0];
    const float* W1     = (const float*)d_in[1];
    const float* b1     = (const float*)d_in[2];
    const float* W2     = (const float*)d_in[3];
    const float* b2     = (const float*)d_in[4];
    const float* keys   = (const float*)d_in[5];
    const float* values = (const float*)d_in[6];
    float* out = (float*)d_out;

    k1_gemm_relu<<<T_TOK / BM, 256>>>(x, W1, b1);
    k2_q<<<128, 256>>>(W2, b2);
    k3_topk<<<T_TOK / 8, 256>>>(keys);
    k4_gather<<<T_TOK, 256>>>(values, out);
}

// round 14
// speedup vs baseline: 1.6026x; 1.1539x over previous
#include <cuda_runtime.h>

// Problem constants (fixed shapes)
#define T_TOK 8192
#define D_IN  1024
#define H1    128
#define QDIM  32
#define HALFD 8
#define KNN   8
#define NKEYS 256

// k1 tiling: 64 tokens x 128 outputs per block, BK=16, 256 threads.
#define BM 64
#define BN 128
#define BK 16
#define NKT (D_IN / BK)   // 64

// smem strides (floats), padded for bank-conflict-free access, 16B-aligned
#define XS_STRIDE 68      // Xs[k][tok]
#define WS_STRIDE 132     // Ws[k][col]
#define HS_STRIDE 136     // hs[tok][col] (epilogue)

#define XS_BUF (BK * XS_STRIDE)          // 1088 floats
#define WS_BUF (BK * WS_STRIDE)          // 2112 floats
#define SMEM_MAIN  ((2 * XS_BUF + 2 * WS_BUF) * 4)          // 25600 B
#define SMEM_EPI   ((BM * HS_STRIDE + QDIM * H1) * 4)       // 51200 B
#define SMEM_BYTES (SMEM_EPI > SMEM_MAIN ? SMEM_EPI : SMEM_MAIN)

// Scratch (device globals: allocation-free rule)
__device__ __align__(16) float g_q[T_TOK * QDIM];   // 1 MB
__device__ float g_wt[T_TOK * 16];                  // 512 KB
__device__ int   g_id[T_TOK * 16];                  // 512 KB

// Packed dual-fp32 FMA (B300 FFMA2, rt~2 confirmed by R12 ncu)
#define FMA2(d, a, b) asm("fma.rn.f32x2 %0, %1, %2, %0;" : "+l"(d) : "l"(a), "l"(b))
// Duplicate scalar into both halves of a packed operand (alu pipe MOVs)
#define DUP2(d, s)    asm("mov.b64 %0, {%1, %1};" : "=l"(d) : "f"(s))

// ---------------------------------------------------------------------------
// Kernel 1 (fused k1+k2): h = relu(x@W1^T + b1); q = h@W2^T + b2 -> g_q
//   256 threads (8 warps, 2 warp-rows x 4 warp-cols), grid 128.
//   Warp tile 32tok x 32col; lane (tr=lane>>2, cg=lane&3): 4 tok x 8 col.
//   Per k per lane: 1 broadcast LDS.128 (a, 1 wf) + 2 broadcast LDS.128
//   (b col-pairs, 1 wf each) + 8 MOV (a-dup, alu) + 16 FMA2 (fma).
//   L1 ~680 wf/kt/SM vs fma 1024 cyc/SMSP/kt -> fma-bound.
//   Epilogue computes q in-SM (h tile never goes to gmem).
// ---------------------------------------------------------------------------
extern __shared__ __align__(16) char smem_raw[];

__global__ __launch_bounds__(256, 1)
void k1_gemm_relu_q(const float* __restrict__ x, const float* __restrict__ W1,
                    const float* __restrict__ b1, const float* __restrict__ W2,
                    const float* __restrict__ b2)
{
    float* Xs = (float*)smem_raw;                       // [2][BK][XS_STRIDE]
    float* Ws = (float*)(smem_raw + 2 * XS_BUF * 4);    // [2][BK][WS_STRIDE]

    const int tid  = threadIdx.x;
    const int lane = tid & 31;
    const int w    = tid >> 5;
    const int wr   = w >> 2;          // warp row (tokens): 0..1
    const int wc   = w & 3;           // warp col (outputs): 0..3
    const int tr   = lane >> 2;       // lane token group: 0..7
    const int cg   = lane & 3;        // lane col group:   0..3
    const int t0   = blockIdx.x * BM;

    const int tokb = (wr << 5) + (tr << 2);   // lane's 4 tokens
    const int colb = (wc << 5) + (cg << 3);   // lane's 8 cols

    // Loader mapping (line-friendly: 8 lines per warp-LDG)
    const int xt  = tid >> 2;          // X token 0..63
    const int xkq = (tid & 3) << 2;    // X k-quad offset
    const int wcA = tid >> 2;          // W col 0..63 (and +64)
    const int wkq = (tid & 3) << 2;    // W k-quad offset

    const float* xp  = x  + (size_t)(t0 + xt) * D_IN + xkq;
    const float* wpA = W1 + (size_t)wcA * D_IN + wkq;
    const float* wpB = W1 + (size_t)(wcA + 64) * D_IN + wkq;

    unsigned long long acc[4][4];   // [token][col-pair]
#pragma unroll
    for (int t = 0; t < 4; t++)
#pragma unroll
        for (int c = 0; c < 4; c++) acc[t][c] = 0ull;

    float4 pX, pWA, pWB;
    pX  = *(const float4*)(xp);
    pWA = *(const float4*)(wpA);
    pWB = *(const float4*)(wpB);

#define STORE_TILE(buf)                                                        \
    do {                                                                       \
        float* xb = Xs + (buf) * XS_BUF;                                       \
        float* wb = Ws + (buf) * WS_BUF;                                       \
        xb[(xkq + 0) * XS_STRIDE + xt] = pX.x;                                 \
        xb[(xkq + 1) * XS_STRIDE + xt] = pX.y;                                 \
        xb[(xkq + 2) * XS_STRIDE + xt] = pX.z;                                 \
        xb[(xkq + 3) * XS_STRIDE + xt] = pX.w;                                 \
        wb[(wkq + 0) * WS_STRIDE + wcA]      = pWA.x;                          \
        wb[(wkq + 1) * WS_STRIDE + wcA]      = pWA.y;                          \
        wb[(wkq + 2) * WS_STRIDE + wcA]      = pWA.z;                          \
        wb[(wkq + 3) * WS_STRIDE + wcA]      = pWA.w;                          \
        wb[(wkq + 0) * WS_STRIDE + wcA + 64] = pWB.x;                          \
        wb[(wkq + 1) * WS_STRIDE + wcA + 64] = pWB.y;                          \
        wb[(wkq + 2) * WS_STRIDE + wcA + 64] = pWB.z;                          \
        wb[(wkq + 3) * WS_STRIDE + wcA + 64] = pWB.w;                          \
    } while (0)

    STORE_TILE(0);
    __syncthreads();

#pragma unroll 1
    for (int kt = 0; kt < NKT; kt++) {
        const int cur = kt & 1;
        if (kt < NKT - 1) {
            const int k0 = (kt + 1) * BK;
            pX  = *(const float4*)(xp + k0);
            pWA = *(const float4*)(wpA + k0);
            pWB = *(const float4*)(wpB + k0);
        }
        const float* xb = Xs + cur * XS_BUF;
        const float* wb = Ws + cur * WS_BUF;
#pragma unroll
        for (int k = 0; k < BK; k++) {
            // a: 4 tokens, one broadcast LDS.128 (8 uniq addrs / warp)
            const float4 a4 = *(const float4*)&xb[k * XS_STRIDE + tokb];
            unsigned long long ad0, ad1, ad2, ad3;
            DUP2(ad0, a4.x); DUP2(ad1, a4.y); DUP2(ad2, a4.z); DUP2(ad3, a4.w);
            // b: 4 natural col-pairs, two broadcast LDS.128 (4 uniq addrs)
            const ulonglong2 b01 = *(const ulonglong2*)&wb[k * WS_STRIDE + colb];
            const ulonglong2 b23 = *(const ulonglong2*)&wb[k * WS_STRIDE + colb + 4];
            FMA2(acc[0][0], ad0, b01.x); FMA2(acc[0][1], ad0, b01.y);
            FMA2(acc[0][2], ad0, b23.x); FMA2(acc[0][3], ad0, b23.y);
            FMA2(acc[1][0], ad1, b01.x); FMA2(acc[1][1], ad1, b01.y);
            FMA2(acc[1][2], ad1, b23.x); FMA2(acc[1][3], ad1, b23.y);
            FMA2(acc[2][0], ad2, b01.x); FMA2(acc[2][1], ad2, b01.y);
            FMA2(acc[2][2], ad2, b23.x); FMA2(acc[2][3], ad2, b23.y);
            FMA2(acc[3][0], ad3, b01.x); FMA2(acc[3][1], ad3, b01.y);
            FMA2(acc[3][2], ad3, b23.x); FMA2(acc[3][3], ad3, b23.y);
        }
        if (kt < NKT - 1) STORE_TILE(cur ^ 1);
        __syncthreads();
    }

    // ---------------- Epilogue: bias+relu -> hs (smem), then q ----------------
    float* hs  = (float*)smem_raw;                               // [64][HS_STRIDE]
    float* W2s = (float*)(smem_raw + BM * HS_STRIDE * 4);        // [128][32] = W2^T

    const float4 bA = __ldg((const float4*)(b1 + colb));
    const float4 bB = __ldg((const float4*)(b1 + colb + 4));
#pragma unroll
    for (int t = 0; t < 4; t++) {
        float4 lo, hi;
        lo.x = __uint_as_float((unsigned)(acc[t][0]))       + bA.x;
        lo.y = __uint_as_float((unsigned)(acc[t][0] >> 32)) + bA.y;
        lo.z = __uint_as_float((unsigned)(acc[t][1]))       + bA.z;
        lo.w = __uint_as_float((unsigned)(acc[t][1] >> 32)) + bA.w;
        hi.x = __uint_as_float((unsigned)(acc[t][2]))       + bB.x;
        hi.y = __uint_as_float((unsigned)(acc[t][2] >> 32)) + bB.y;
        hi.z = __uint_as_float((unsigned)(acc[t][3]))       + bB.z;
        hi.w = __uint_as_float((unsigned)(acc[t][3] >> 32)) + bB.w;
        lo.x = fmaxf(lo.x, 0.f); lo.y = fmaxf(lo.y, 0.f);
        lo.z = fmaxf(lo.z, 0.f); lo.w = fmaxf(lo.w, 0.f);
        hi.x = fmaxf(hi.x, 0.f); hi.y = fmaxf(hi.y, 0.f);
        hi.z = fmaxf(hi.z, 0.f); hi.w = fmaxf(hi.w, 0.f);
        *(float4*)&hs[(tokb + t) * HS_STRIDE + colb]     = lo;
        *(float4*)&hs[(tokb + t) * HS_STRIDE + colb + 4] = hi;
    }

    // W2^T into smem: W2 is [c][j] (32 x 128); store W2s[j*32 + c]
#pragma unroll
    for (int idx = tid; idx < QDIM * H1; idx += 256) {
        const int c = idx >> 7, j = idx & 127;
        W2s[j * QDIM + c] = W2[idx];
    }
    __syncthreads();

    // q: thread -> token tid>>2, q-dims (tid&3)*8..+7. j-order matches old k2
    {
        const int tok = tid >> 2;
        const int qg  = (tid & 3) << 3;
        float4 qa = __ldg((const float4*)(b2 + qg));
        float4 qb = __ldg((const float4*)(b2 + qg + 4));
#pragma unroll 8
        for (int j = 0; j < H1; j += 4) {
            const float4 h4 = *(const float4*)&hs[tok * HS_STRIDE + j];
#pragma unroll
            for (int jj = 0; jj < 4; jj++) {
                const float hv = (jj == 0) ? h4.x : (jj == 1) ? h4.y
                               : (jj == 2) ? h4.z : h4.w;
                const float4 wA = *(const float4*)&W2s[(j + jj) * QDIM + qg];
                const float4 wB = *(const float4*)&W2s[(j + jj) * QDIM + qg + 4];
                qa.x = fmaf(hv, wA.x, qa.x); qa.y = fmaf(hv, wA.y, qa.y);
                qa.z = fmaf(hv, wA.z, qa.z); qa.w = fmaf(hv, wA.w, qa.w);
                qb.x = fmaf(hv, wB.x, qb.x); qb.y = fmaf(hv, wB.y, qb.y);
                qb.z = fmaf(hv, wB.z, qb.z); qb.w = fmaf(hv, wB.w, qb.w);
            }
        }
        *(float4*)&g_q[(size_t)(t0 + tok) * QDIM + qg]     = qa;
        *(float4*)&g_q[(size_t)(t0 + tok) * QDIM + qg + 4] = qb;
    }
}

// ---------------------------------------------------------------------------
// Kernel 3: scores + top-k + combine + softmax (R9-proven version)
// Tie-breaking matches lax.top_k (lowest index first).
// ---------------------------------------------------------------------------
__global__ __launch_bounds__(256, 1)
void k3_topk(const float* __restrict__ keys)
{
    __shared__ float ks[2 * 2 * NKEYS * HALFD];   // 32 KB
    __shared__ float sc_s[8][2][2][KNN];
    __shared__ int   id_s[8][2][2][KNN];
    __shared__ float fsc_s[8][2][KNN];
    __shared__ int   fid_s[8][2][KNN];

    const int tid = threadIdx.x;
    for (int i = tid; i < 2 * 2 * NKEYS * HALFD; i += 256) ks[i] = keys[i];
    __syncthreads();

    const int w    = tid >> 5;
    const int lane = tid & 31;
    const int t    = blockIdx.x * 8 + w;
    const float myq = g_q[(size_t)t * QDIM + lane];
    const float NEGINF = __uint_as_float(0xff800000u);

    // 4 units: (head, side)
#pragma unroll
    for (int u = 0; u < 4; u++) {
        const int h = u >> 1, side = u & 1;
        float qv[HALFD];
#pragma unroll
        for (int c = 0; c < HALFD; c++)
            qv[c] = __shfl_sync(0xffffffffu, myq, h * 16 + side * 8 + c);

        float s[8];  // lane owns keys n = i*32 + lane
#pragma unroll
        for (int i = 0; i < 8; i++) {
            const int n = i * 32 + lane;
            const float4 k0 = *(const float4*)&ks[(u * NKEYS + n) * HALFD];
            const float4 k1 = *(const float4*)&ks[(u * NKEYS + n) * HALFD + 4];
            s[i] = qv[0] * k0.x + qv[1] * k0.y + qv[2] * k0.z + qv[3] * k0.w
                 + qv[4] * k1.x + qv[5] * k1.y + qv[6] * k1.z + qv[7] * k1.w;
        }
#pragma unroll
        for (int r = 0; r < KNN; r++) {
            float bv = NEGINF; int bn = 0x7fffffff;
#pragma unroll
            for (int i = 0; i < 8; i++)
                if (s[i] > bv) { bv = s[i]; bn = i * 32 + lane; }
#pragma unroll
            for (int off = 16; off; off >>= 1) {
                const float ov = __shfl_xor_sync(0xffffffffu, bv, off);
                const int   on = __shfl_xor_sync(0xffffffffu, bn, off);
                if (ov > bv || (ov == bv && on < bn)) { bv = ov; bn = on; }
            }
            if (lane == 0) { sc_s[w][h][side][r] = bv; id_s[w][h][side][r] = bn; }
            if ((bn & 31) == lane) s[bn >> 5] = NEGINF;   // kill winner
        }
    }
    __syncwarp();

    // Combine per head: 64 combos = sc1[a] + sc2[b], flat c = a*8 + b
#pragma unroll
    for (int h = 0; h < 2; h++) {
        float v0 = sc_s[w][h][0][lane >> 3]       + sc_s[w][h][1][lane & 7];
        float v1 = sc_s[w][h][0][(lane >> 3) + 4] + sc_s[w][h][1][lane & 7];
#pragma unroll
        for (int r = 0; r < KNN; r++) {
            float bv = v0; int bc = lane;
            if (v1 > bv) { bv = v1; bc = lane + 32; }
#pragma unroll
            for (int off = 16; off; off >>= 1) {
                const float ov = __shfl_xor_sync(0xffffffffu, bv, off);
                const int   oc = __shfl_xor_sync(0xffffffffu, bc, off);
                if (ov > bv || (ov == bv && oc < bc)) { bv = ov; bc = oc; }
            }
            if (lane == 0) {
                fsc_s[w][h][r] = bv;
                const int a = bc >> 3, b = bc & 7;
                fid_s[w][h][r] = id_s[w][h][0][a] * NKEYS + id_s[w][h][1][b];
            }
            if (bc == lane)      v0 = NEGINF;
            if (bc == lane + 32) v1 = NEGINF;
        }
    }
    __syncwarp();

    // Softmax over 8 per head; lanes 0..15 each handle one (h,k) output
    if (lane < 16) {
        const int h = lane >> 3, kk = lane & 7;
        float m = NEGINF;
#pragma unroll
        for (int i = 0; i < KNN; i++) m = fmaxf(m, fsc_s[w][h][i]);
        float den = 0.f;
#pragma unroll
        for (int i = 0; i < KNN; i++) den += expf(fsc_s[w][h][i] - m);
        const float wt = expf(fsc_s[w][h][kk] - m) / den;
        g_wt[t * 16 + lane] = wt;
        g_id[t * 16 + lane] = fid_s[w][h][kk];
    }
}

// ---------------------------------------------------------------------------
// Kernel 4: out[t] = sum_{k<16} w_k * values[idx_k]  (R9/R13-proven: ~53us)
// ---------------------------------------------------------------------------
__global__ __launch_bounds__(256, 1)
void k4_gather(const float* __restrict__ values, float* __restrict__ out)
{
    __shared__ float ws[16];
    __shared__ int   is[16];
    const int t = blockIdx.x;
    if (threadIdx.x < 16) {
        ws[threadIdx.x] = g_wt[t * 16 + threadIdx.x];
        is[threadIdx.x] = g_id[t * 16 + threadIdx.x];
    }
    __syncthreads();
    const int col = threadIdx.x << 2;
    float4 acc = make_float4(0.f, 0.f, 0.f, 0.f);
#pragma unroll
    for (int k = 0; k < 16; k++) {
        const float4 v = __ldg((const float4*)(values + (size_t)is[k] * D_IN + col));
        const float wk = ws[k];
        acc.x = fmaf(wk, v.x, acc.x);
        acc.y = fmaf(wk, v.y, acc.y);
        acc.z = fmaf(wk, v.z, acc.z);
        acc.w = fmaf(wk, v.w, acc.w);
    }
    *(float4*)(out + (size_t)t * D_IN + col) = acc;
}

// ---------------------------------------------------------------------------
extern "C" void kernel_launch(void* const* d_in, const int* in_sizes, int n_in,
                              void* d_out, int out_size)
{
    const float* x      = (const float*)d_in[0];
    const float* W1     = (const float*)d_in[1];
    const float* b1     = (const float*)d_in[2];
    const float* W2     = (const float*)d_in[3];
    const float* b2     = (const float*)d_in[4];
    const float* keys   = (const float*)d_in[5];
    const float* values = (const float*)d_in[6];
    float* out = (float*)d_out;

    cudaFuncSetAttribute(k1_gemm_relu_q,
                         cudaFuncAttributeMaxDynamicSharedMemorySize, SMEM_BYTES);

    k1_gemm_relu_q<<<T_TOK / BM, 256, SMEM_BYTES>>>(x, W1, b1, W2, b2);
    k3_topk<<<T_TOK / 8, 256>>>(keys);
    k4_gather<<<T_TOK, 256>>>(values, out);
}

// round 15
// speedup vs baseline: 1.6056x; 1.0019x over previous
#include <cuda_runtime.h>

// Problem constants (fixed shapes)
#define T_TOK 8192
#define D_IN  1024
#define H1    128
#define QDIM  32
#define HALFD 8
#define KNN   8
#define NKEYS 256

// k1 tiling: 64 tokens x 128 outputs per block, BK=16, 256 threads.
#define BM 64
#define BN 128
#define BK 16
#define NKT (D_IN / BK)   // 64

// smem strides (floats), padded for bank-conflict-free access, 16B-aligned
#define XS_STRIDE 68      // Xs[k][tok]
#define WS_STRIDE 132     // Ws[k][col]
#define HS_STRIDE 136     // hs[tok][col] (epilogue)

#define XS_BUF (BK * XS_STRIDE)          // 1088 floats
#define WS_BUF (BK * WS_STRIDE)          // 2112 floats
#define SMEM_MAIN  ((2 * XS_BUF + 2 * WS_BUF) * 4)          // 25600 B
#define SMEM_EPI   ((BM * HS_STRIDE + QDIM * H1) * 4)       // 51200 B
#define SMEM_BYTES (SMEM_EPI > SMEM_MAIN ? SMEM_EPI : SMEM_MAIN)

// Scratch (device globals: allocation-free rule)
__device__ __align__(16) float g_q[T_TOK * QDIM];   // 1 MB
__device__ float g_wt[T_TOK * 16];                  // 512 KB
__device__ int   g_id[T_TOK * 16];                  // 512 KB

// Packed dual-fp32 FMA (B300 FFMA2, rt~2 confirmed by R12 ncu)
#define FMA2(d, a, b) asm("fma.rn.f32x2 %0, %1, %2, %0;" : "+l"(d) : "l"(a), "l"(b))
// Duplicate scalar into both halves of a packed operand (alu pipe MOVs)
#define DUP2(d, s)    asm("mov.b64 %0, {%1, %1};" : "=l"(d) : "f"(s))

// ---------------------------------------------------------------------------
// Kernel 1 (fused k1+k2): h = relu(x@W1^T + b1); q = h@W2^T + b2 -> g_q
//   256 threads (8 warps, 2 warp-rows x 4 warp-cols), grid 128.
//   Warp tile 32tok x 32col; lane (tr=lane>>2, cg=lane&3): 4 tok x 8 col.
//   Per k per lane: 1 broadcast LDS.128 (a, 1 wf) + 2 broadcast LDS.128
//   (b col-pairs, 1 wf each) + 8 MOV (a-dup, alu) + 16 FMA2 (fma).
//   L1 ~680 wf/kt/SM vs fma 1024 cyc/SMSP/kt -> fma-bound.
//   Epilogue computes q in-SM (h tile never goes to gmem).
// ---------------------------------------------------------------------------
extern __shared__ __align__(16) char smem_raw[];

__global__ __launch_bounds__(256, 1)
void k1_gemm_relu_q(const float* __restrict__ x, const float* __restrict__ W1,
                    const float* __restrict__ b1, const float* __restrict__ W2,
                    const float* __restrict__ b2)
{
    float* Xs = (float*)smem_raw;                       // [2][BK][XS_STRIDE]
    float* Ws = (float*)(smem_raw + 2 * XS_BUF * 4);    // [2][BK][WS_STRIDE]

    const int tid  = threadIdx.x;
    const int lane = tid & 31;
    const int w    = tid >> 5;
    const int wr   = w >> 2;          // warp row (tokens): 0..1
    const int wc   = w & 3;           // warp col (outputs): 0..3
    const int tr   = lane >> 2;       // lane token group: 0..7
    const int cg   = lane & 3;        // lane col group:   0..3
    const int t0   = blockIdx.x * BM;

    const int tokb = (wr << 5) + (tr << 2);   // lane's 4 tokens
    const int colb = (wc << 5) + (cg << 3);   // lane's 8 cols

    // Loader mapping (line-friendly: 8 lines per warp-LDG)
    const int xt  = tid >> 2;          // X token 0..63
    const int xkq = (tid & 3) << 2;    // X k-quad offset
    const int wcA = tid >> 2;          // W col 0..63 (and +64)
    const int wkq = (tid & 3) << 2;    // W k-quad offset

    const float* xp  = x  + (size_t)(t0 + xt) * D_IN + xkq;
    const float* wpA = W1 + (size_t)wcA * D_IN + wkq;
    const float* wpB = W1 + (size_t)(wcA + 64) * D_IN + wkq;

    unsigned long long acc[4][4];   // [token][col-pair]
#pragma unroll
    for (int t = 0; t < 4; t++)
#pragma unroll
        for (int c = 0; c < 4; c++) acc[t][c] = 0ull;

    float4 pX, pWA, pWB;
    pX  = *(const float4*)(xp);
    pWA = *(const float4*)(wpA);
    pWB = *(const float4*)(wpB);

#define STORE_TILE(buf)                                                        \
    do {                                                                       \
        float* xb = Xs + (buf) * XS_BUF;                                       \
        float* wb = Ws + (buf) * WS_BUF;                                       \
        xb[(xkq + 0) * XS_STRIDE + xt] = pX.x;                                 \
        xb[(xkq + 1) * XS_STRIDE + xt] = pX.y;                                 \
        xb[(xkq + 2) * XS_STRIDE + xt] = pX.z;                                 \
        xb[(xkq + 3) * XS_STRIDE + xt] = pX.w;                                 \
        wb[(wkq + 0) * WS_STRIDE + wcA]      = pWA.x;                          \
        wb[(wkq + 1) * WS_STRIDE + wcA]      = pWA.y;                          \
        wb[(wkq + 2) * WS_STRIDE + wcA]      = pWA.z;                          \
        wb[(wkq + 3) * WS_STRIDE + wcA]      = pWA.w;                          \
        wb[(wkq + 0) * WS_STRIDE + wcA + 64] = pWB.x;                          \
        wb[(wkq + 1) * WS_STRIDE + wcA + 64] = pWB.y;                          \
        wb[(wkq + 2) * WS_STRIDE + wcA + 64] = pWB.z;                          \
        wb[(wkq + 3) * WS_STRIDE + wcA + 64] = pWB.w;                          \
    } while (0)

    STORE_TILE(0);
    __syncthreads();

#pragma unroll 1
    for (int kt = 0; kt < NKT; kt++) {
        const int cur = kt & 1;
        if (kt < NKT - 1) {
            const int k0 = (kt + 1) * BK;
            pX  = *(const float4*)(xp + k0);
            pWA = *(const float4*)(wpA + k0);
            pWB = *(const float4*)(wpB + k0);
        }
        const float* xb = Xs + cur * XS_BUF;
        const float* wb = Ws + cur * WS_BUF;
#pragma unroll
        for (int k = 0; k < BK; k++) {
            // a: 4 tokens, one broadcast LDS.128 (8 uniq addrs / warp)
            const float4 a4 = *(const float4*)&xb[k * XS_STRIDE + tokb];
            unsigned long long ad0, ad1, ad2, ad3;
            DUP2(ad0, a4.x); DUP2(ad1, a4.y); DUP2(ad2, a4.z); DUP2(ad3, a4.w);
            // b: 4 natural col-pairs, two broadcast LDS.128 (4 uniq addrs)
            const ulonglong2 b01 = *(const ulonglong2*)&wb[k * WS_STRIDE + colb];
            const ulonglong2 b23 = *(const ulonglong2*)&wb[k * WS_STRIDE + colb + 4];
            FMA2(acc[0][0], ad0, b01.x); FMA2(acc[0][1], ad0, b01.y);
            FMA2(acc[0][2], ad0, b23.x); FMA2(acc[0][3], ad0, b23.y);
            FMA2(acc[1][0], ad1, b01.x); FMA2(acc[1][1], ad1, b01.y);
            FMA2(acc[1][2], ad1, b23.x); FMA2(acc[1][3], ad1, b23.y);
            FMA2(acc[2][0], ad2, b01.x); FMA2(acc[2][1], ad2, b01.y);
            FMA2(acc[2][2], ad2, b23.x); FMA2(acc[2][3], ad2, b23.y);
            FMA2(acc[3][0], ad3, b01.x); FMA2(acc[3][1], ad3, b01.y);
            FMA2(acc[3][2], ad3, b23.x); FMA2(acc[3][3], ad3, b23.y);
        }
        if (kt < NKT - 1) STORE_TILE(cur ^ 1);
        __syncthreads();
    }

    // ---------------- Epilogue: bias+relu -> hs (smem), then q ----------------
    float* hs  = (float*)smem_raw;                               // [64][HS_STRIDE]
    float* W2s = (float*)(smem_raw + BM * HS_STRIDE * 4);        // [128][32] = W2^T

    const float4 bA = __ldg((const float4*)(b1 + colb));
    const float4 bB = __ldg((const float4*)(b1 + colb + 4));
#pragma unroll
    for (int t = 0; t < 4; t++) {
        float4 lo, hi;
        lo.x = __uint_as_float((unsigned)(acc[t][0]))       + bA.x;
        lo.y = __uint_as_float((unsigned)(acc[t][0] >> 32)) + bA.y;
        lo.z = __uint_as_float((unsigned)(acc[t][1]))       + bA.z;
        lo.w = __uint_as_float((unsigned)(acc[t][1] >> 32)) + bA.w;
        hi.x = __uint_as_float((unsigned)(acc[t][2]))       + bB.x;
        hi.y = __uint_as_float((unsigned)(acc[t][2] >> 32)) + bB.y;
        hi.z = __uint_as_float((unsigned)(acc[t][3]))       + bB.z;
        hi.w = __uint_as_float((unsigned)(acc[t][3] >> 32)) + bB.w;
        lo.x = fmaxf(lo.x, 0.f); lo.y = fmaxf(lo.y, 0.f);
        lo.z = fmaxf(lo.z, 0.f); lo.w = fmaxf(lo.w, 0.f);
        hi.x = fmaxf(hi.x, 0.f); hi.y = fmaxf(hi.y, 0.f);
        hi.z = fmaxf(hi.z, 0.f); hi.w = fmaxf(hi.w, 0.f);
        *(float4*)&hs[(tokb + t) * HS_STRIDE + colb]     = lo;
        *(float4*)&hs[(tokb + t) * HS_STRIDE + colb + 4] = hi;
    }

    // W2^T into smem: W2 is [c][j] (32 x 128); store W2s[j*32 + c]
#pragma unroll
    for (int idx = tid; idx < QDIM * H1; idx += 256) {
        const int c = idx >> 7, j = idx & 127;
        W2s[j * QDIM + c] = W2[idx];
    }
    __syncthreads();

    // q: thread -> token tid>>2, q-dims (tid&3)*8..+7. j-order matches old k2
    {
        const int tok = tid >> 2;
        const int qg  = (tid & 3) << 3;
        float4 qa = __ldg((const float4*)(b2 + qg));
        float4 qb = __ldg((const float4*)(b2 + qg + 4));
#pragma unroll 8
        for (int j = 0; j < H1; j += 4) {
            const float4 h4 = *(const float4*)&hs[tok * HS_STRIDE + j];
#pragma unroll
            for (int jj = 0; jj < 4; jj++) {
                const float hv = (jj == 0) ? h4.x : (jj == 1) ? h4.y
                               : (jj == 2) ? h4.z : h4.w;
                const float4 wA = *(const float4*)&W2s[(j + jj) * QDIM + qg];
                const float4 wB = *(const float4*)&W2s[(j + jj) * QDIM + qg + 4];
                qa.x = fmaf(hv, wA.x, qa.x); qa.y = fmaf(hv, wA.y, qa.y);
                qa.z = fmaf(hv, wA.z, qa.z); qa.w = fmaf(hv, wA.w, qa.w);
                qb.x = fmaf(hv, wB.x, qb.x); qb.y = fmaf(hv, wB.y, qb.y);
                qb.z = fmaf(hv, wB.z, qb.z); qb.w = fmaf(hv, wB.w, qb.w);
            }
        }
        *(float4*)&g_q[(size_t)(t0 + tok) * QDIM + qg]     = qa;
        *(float4*)&g_q[(size_t)(t0 + tok) * QDIM + qg + 4] = qb;
    }
}

// ---------------------------------------------------------------------------
// Kernel 3: scores + top-k + combine + softmax (R9-proven version)
// Tie-breaking matches lax.top_k (lowest index first).
// ---------------------------------------------------------------------------
__global__ __launch_bounds__(256, 1)
void k3_topk(const float* __restrict__ keys)
{
    __shared__ float ks[2 * 2 * NKEYS * HALFD];   // 32 KB
    __shared__ float sc_s[8][2][2][KNN];
    __shared__ int   id_s[8][2][2][KNN];
    __shared__ float fsc_s[8][2][KNN];
    __shared__ int   fid_s[8][2][KNN];

    const int tid = threadIdx.x;
    for (int i = tid; i < 2 * 2 * NKEYS * HALFD; i += 256) ks[i] = keys[i];
    __syncthreads();

    const int w    = tid >> 5;
    const int lane = tid & 31;
    const int t    = blockIdx.x * 8 + w;
    const float myq = g_q[(size_t)t * QDIM + lane];
    const float NEGINF = __uint_as_float(0xff800000u);

    // 4 units: (head, side)
#pragma unroll
    for (int u = 0; u < 4; u++) {
        const int h = u >> 1, side = u & 1;
        float qv[HALFD];
#pragma unroll
        for (int c = 0; c < HALFD; c++)
            qv[c] = __shfl_sync(0xffffffffu, myq, h * 16 + side * 8 + c);

        float s[8];  // lane owns keys n = i*32 + lane
#pragma unroll
        for (int i = 0; i < 8; i++) {
            const int n = i * 32 + lane;
            const float4 k0 = *(const float4*)&ks[(u * NKEYS + n) * HALFD];
            const float4 k1 = *(const float4*)&ks[(u * NKEYS + n) * HALFD + 4];
            s[i] = qv[0] * k0.x + qv[1] * k0.y + qv[2] * k0.z + qv[3] * k0.w
                 + qv[4] * k1.x + qv[5] * k1.y + qv[6] * k1.z + qv[7] * k1.w;
        }
#pragma unroll
        for (int r = 0; r < KNN; r++) {
            float bv = NEGINF; int bn = 0x7fffffff;
#pragma unroll
            for (int i = 0; i < 8; i++)
                if (s[i] > bv) { bv = s[i]; bn = i * 32 + lane; }
#pragma unroll
            for (int off = 16; off; off >>= 1) {
                const float ov = __shfl_xor_sync(0xffffffffu, bv, off);
                const int   on = __shfl_xor_sync(0xffffffffu, bn, off);
                if (ov > bv || (ov == bv && on < bn)) { bv = ov; bn = on; }
            }
            if (lane == 0) { sc_s[w][h][side][r] = bv; id_s[w][h][side][r] = bn; }
            if ((bn & 31) == lane) s[bn >> 5] = NEGINF;   // kill winner
        }
    }
    __syncwarp();

    // Combine per head: 64 combos = sc1[a] + sc2[b], flat c = a*8 + b
#pragma unroll
    for (int h = 0; h < 2; h++) {
        float v0 = sc_s[w][h][0][lane >> 3]       + sc_s[w][h][1][lane & 7];
        float v1 = sc_s[w][h][0][(lane >> 3) + 4] + sc_s[w][h][1][lane & 7];
#pragma unroll
        for (int r = 0; r < KNN; r++) {
            float bv = v0; int bc = lane;
            if (v1 > bv) { bv = v1; bc = lane + 32; }
#pragma unroll
            for (int off = 16; off; off >>= 1) {
                const float ov = __shfl_xor_sync(0xffffffffu, bv, off);
                const int   oc = __shfl_xor_sync(0xffffffffu, bc, off);
                if (ov > bv || (ov == bv && oc < bc)) { bv = ov; bc = oc; }
            }
            if (lane == 0) {
                fsc_s[w][h][r] = bv;
                const int a = bc >> 3, b = bc & 7;
                fid_s[w][h][r] = id_s[w][h][0][a] * NKEYS + id_s[w][h][1][b];
            }
            if (bc == lane)      v0 = NEGINF;
            if (bc == lane + 32) v1 = NEGINF;
        }
    }
    __syncwarp();

    // Softmax over 8 per head; lanes 0..15 each handle one (h,k) output
    if (lane < 16) {
        const int h = lane >> 3, kk = lane & 7;
        float m = NEGINF;
#pragma unroll
        for (int i = 0; i < KNN; i++) m = fmaxf(m, fsc_s[w][h][i]);
        float den = 0.f;
#pragma unroll
        for (int i = 0; i < KNN; i++) den += expf(fsc_s[w][h][i] - m);
        const float wt = expf(fsc_s[w][h][kk] - m) / den;
        g_wt[t * 16 + lane] = wt;
        g_id[t * 16 + lane] = fid_s[w][h][kk];
    }
}

// ---------------------------------------------------------------------------
// Kernel 4: out[t] = sum_{k<16} w_k * values[idx_k]  (R9/R13-proven: ~53us)
// ---------------------------------------------------------------------------
__global__ __launch_bounds__(256, 1)
void k4_gather(const float* __restrict__ values, float* __restrict__ out)
{
    __shared__ float ws[16];
    __shared__ int   is[16];
    const int t = blockIdx.x;
    if (threadIdx.x < 16) {
        ws[threadIdx.x] = g_wt[t * 16 + threadIdx.x];
        is[threadIdx.x] = g_id[t * 16 + threadIdx.x];
    }
    __syncthreads();
    const int col = threadIdx.x << 2;
    float4 acc = make_float4(0.f, 0.f, 0.f, 0.f);
#pragma unroll
    for (int k = 0; k < 16; k++) {
        const float4 v = __ldg((const float4*)(values + (size_t)is[k] * D_IN + col));
        const float wk = ws[k];
        acc.x = fmaf(wk, v.x, acc.x);
        acc.y = fmaf(wk, v.y, acc.y);
        acc.z = fmaf(wk, v.z, acc.z);
        acc.w = fmaf(wk, v.w, acc.w);
    }
    *(float4*)(out + (size_t)t * D_IN + col) = acc;
}

// ---------------------------------------------------------------------------
extern "C" void kernel_launch(void* const* d_in, const int* in_sizes, int n_in,
                              void* d_out, int out_size)
{
    const float* x      = (const float*)d_in[0];
    const float* W1     = (const float*)d_in[1];
    const float* b1     = (const float*)d_in[2];
    const float* W2     = (const float*)d_in[3];
    const float* b2     = (const float*)d_in[4];
    const float* keys   = (const float*)d_in[5];
    const float* values = (const float*)d_in[6];
    float* out = (float*)d_out;

    cudaFuncSetAttribute(k1_gemm_relu_q,
                         cudaFuncAttributeMaxDynamicSharedMemorySize, SMEM_BYTES);

    k1_gemm_relu_q<<<T_TOK / BM, 256, SMEM_BYTES>>>(x, W1, b1, W2, b2);
    k3_topk<<<T_TOK / 8, 256>>>(keys);
    k4_gather<<<T_TOK, 256>>>(values, out);
}